// round 9
// baseline (speedup 1.0000x reference)
#include <cuda_runtime.h>
#include <math_constants.h>

#define WIN    400
#define RNUM   64
#define BNUM   2
#define ANUM   3
#define KSEL   8
#define WPC    2                  // windows per tile
#define SPAN   (WIN * WPC)        // 800 floats
#define NV4S   (SPAN / 4)         // 200 vec4 per row span
#define NWG    500                // window-groups (1000 / WPC)
#define NTILES (NWG * ANUM)       // 1500
#define NPERS  740                // persistent CTAs = 148 SMs * 5

__global__ __launch_bounds__(256, 5) void win_topk_kernel(
    const float* __restrict__ mixed,    // [B, S]
    const float* __restrict__ ref,      // [A, R, S]
    const float* __restrict__ weights,  // [K]
    float* __restrict__ out,            // [6*W] scores ++ [6*W*K] idx (as float)
    int S, int W, int write_idx)
{
    const int tid  = threadIdx.x;
    const int warp = tid >> 5;
    const int lane = tid & 31;

    __shared__ __align__(16) float sm_mixed[BNUM][SPAN];
    __shared__ float sm_scores[BNUM][WPC][RNUM];
    __shared__ float sm_w[KSEL];

    if (tid < KSEL) sm_w[tid] = weights[tid];

    // Static persistent schedule: tiles blockIdx.x, +740, +1480.
    for (int t = blockIdx.x; t < NTILES; t += NPERS) {
        const int a  = t / NWG;
        const int wg = t % NWG;
        const long base = (long)wg * SPAN;

        __syncthreads();   // smem safe to overwrite (prev tile fully consumed)

        // Stage mixed span (both batch rows) into shared, vectorized.
        {
            const float4* m4 = (const float4*)mixed;  // 16B-aligned spans
            float4* sm4 = (float4*)&sm_mixed[0][0];
            for (int i = tid; i < BNUM * NV4S; i += 256) {   // 400 vec4
                int b = i / NV4S, v = i % NV4S;
                sm4[i] = m4[((long)b * S + base) / 4 + v];
            }
        }
        __syncthreads();

        // Each warp streams 8 ref rows over the 3.2KB span (2 win, 2 batch).
        {
            const float4* sm0 = (const float4*)&sm_mixed[0][0];
            const float4* sm1 = (const float4*)&sm_mixed[1][0];
            const float* refa = ref + ((long)a * RNUM) * S + base;

            #pragma unroll
            for (int i = 0; i < RNUM / 8; i++) {
                const int r = warp * (RNUM / 8) + i;
                const float4* row4 = (const float4*)(refa + (long)r * S);

                float s00 = 0.f, s01 = 0.f;   // batch0: win0, win1
                float s10 = 0.f, s11 = 0.f;   // batch1: win0, win1
                #pragma unroll
                for (int j = 0; j < 6; j++) {   // 192 vec4 full-warp
                    int v = lane + j * 32;
                    float4 rv = __ldg(&row4[v]);
                    float4 m0 = sm0[v];
                    float4 m1 = sm1[v];
                    float c0 = rv.x * m0.x;
                    c0 = fmaf(rv.y, m0.y, c0);
                    c0 = fmaf(rv.z, m0.z, c0);
                    c0 = fmaf(rv.w, m0.w, c0);
                    float c1 = rv.x * m1.x;
                    c1 = fmaf(rv.y, m1.y, c1);
                    c1 = fmaf(rv.z, m1.z, c1);
                    c1 = fmaf(rv.w, m1.w, c1);
                    if (v < WIN / 4) { s00 += c0; s10 += c1; }
                    else             { s01 += c0; s11 += c1; }
                }
                if (lane < NV4S - 192) {        // tail: vec4 192..199 (win1)
                    int v = 192 + lane;
                    float4 rv = __ldg(&row4[v]);
                    float4 m0 = sm0[v];
                    float4 m1 = sm1[v];
                    float c0 = rv.x * m0.x;
                    c0 = fmaf(rv.y, m0.y, c0);
                    c0 = fmaf(rv.z, m0.z, c0);
                    c0 = fmaf(rv.w, m0.w, c0);
                    float c1 = rv.x * m1.x;
                    c1 = fmaf(rv.y, m1.y, c1);
                    c1 = fmaf(rv.z, m1.z, c1);
                    c1 = fmaf(rv.w, m1.w, c1);
                    s01 += c0; s11 += c1;
                }
                // Warp reductions (4 values)
                #pragma unroll
                for (int off = 16; off > 0; off >>= 1) {
                    s00 += __shfl_down_sync(0xffffffffu, s00, off);
                    s01 += __shfl_down_sync(0xffffffffu, s01, off);
                    s10 += __shfl_down_sync(0xffffffffu, s10, off);
                    s11 += __shfl_down_sync(0xffffffffu, s11, off);
                }
                if (lane == 0) {
                    sm_scores[0][0][r] = s00 * (1.0f / WIN);
                    sm_scores[0][1][r] = s01 * (1.0f / WIN);
                    sm_scores[1][0][r] = s10 * (1.0f / WIN);
                    sm_scores[1][1][r] = s11 * (1.0f / WIN);
                }
            }
        }
        __syncthreads();

        // Top-K (K=8) over 64 refs; warps 0..3 handle the 4 (b, win) combos.
        if (warp < BNUM * WPC) {
            const int b   = warp >> 1;
            const int win = warp & 1;
            float v0 = sm_scores[b][win][lane];
            float v1 = sm_scores[b][win][lane + 32];
            float acc = 0.f;

            const int  wglob = wg * WPC + win;
            const long ow    = ((long)b * ANUM + a) * W + wglob;
            const long ibase = (long)BNUM * ANUM * W + ow * KSEL;

            #pragma unroll
            for (int k = 0; k < KSEL; k++) {
                float bv; int bi;
                if (v0 >= v1) { bv = v0; bi = lane; }    // ties -> lower index
                else          { bv = v1; bi = lane + 32; }
                #pragma unroll
                for (int off = 16; off > 0; off >>= 1) {
                    float ov = __shfl_xor_sync(0xffffffffu, bv, off);
                    int   oi = __shfl_xor_sync(0xffffffffu, bi, off);
                    if (ov > bv || (ov == bv && oi < bi)) { bv = ov; bi = oi; }
                }
                acc = fmaf(bv, sm_w[k], acc);
                if (write_idx && lane == 0) out[ibase + k] = (float)bi;
                if (bi == lane)      v0 = -CUDART_INF_F;
                if (bi == lane + 32) v1 = -CUDART_INF_F;
            }
            if (lane == 0) out[ow] = acc;
        }
    }
}

extern "C" void kernel_launch(void* const* d_in, const int* in_sizes, int n_in,
                              void* d_out, int out_size) {
    const float* mixed   = (const float*)d_in[0];
    const float* ref     = (const float*)d_in[1];
    const float* weights = (const float*)d_in[2];
    float* out = (float*)d_out;

    const int S = in_sizes[0] / BNUM;      // 400000
    const int W = S / WIN;                 // 1000
    const int write_idx = (out_size >= BNUM * ANUM * W * (1 + KSEL)) ? 1 : 0;

    win_topk_kernel<<<NPERS, 256>>>(mixed, ref, weights, out, S, W, write_idx);
}

// round 10
// speedup vs baseline: 1.1689x; 1.1689x over previous
#include <cuda_runtime.h>
#include <math_constants.h>

#define WIN   400
#define RNUM  64
#define BNUM  2
#define ANUM  3
#define KSEL  8
#define WPC   2                 // windows per CTA
#define SPAN  (WIN * WPC)       // 800 floats
#define NV4S  (SPAN / 4)        // 200 float4 per row span

__global__ __launch_bounds__(256, 8) void win_topk_kernel(
    const float* __restrict__ mixed,    // [B, S]
    const float* __restrict__ ref,      // [A, R, S]
    const float* __restrict__ weights,  // [K]
    float* __restrict__ out,            // [6*W] scores ++ [6*W*K] idx (as float)
    int S, int W, int write_idx)
{
    const int wg   = blockIdx.x;        // window-pair index
    const int a    = blockIdx.y;
    const int tid  = threadIdx.x;
    const int warp = tid >> 5;
    const int lane = tid & 31;

    __shared__ __align__(16) float sm_mixed[BNUM][SPAN];
    __shared__ float sm_scores[BNUM][WPC][RNUM];
    __shared__ float sm_w[KSEL];

    const long base = (long)wg * SPAN;

    // Stage mixed span (both batch rows) into shared, vectorized.
    {
        const float4* m4 = (const float4*)mixed;  // S % 4 == 0, base % 4 == 0
        float4* sm4 = (float4*)&sm_mixed[0][0];
        const int nv = BNUM * NV4S;  // 400 float4
        for (int i = tid; i < nv; i += blockDim.x) {
            int b = i / NV4S, v = i % NV4S;
            sm4[b * NV4S + v] = m4[((long)b * S + base) / 4 + v];
        }
        if (tid < KSEL) sm_w[tid] = weights[tid];
    }
    __syncthreads();

    // Each warp streams 8 ref rows over the 3200B span (2 windows, 2 batches).
    {
        const float4* sm0 = (const float4*)&sm_mixed[0][0];
        const float4* sm1 = (const float4*)&sm_mixed[1][0];
        const float* refa = ref + ((long)a * RNUM) * S + base;

        #pragma unroll
        for (int i = 0; i < RNUM / 8; i++) {
            const int r = warp * (RNUM / 8) + i;
            const float4* row4 = (const float4*)(refa + (long)r * S);

            float s00 = 0.f, s01 = 0.f;   // batch0: win0, win1
            float s10 = 0.f, s11 = 0.f;   // batch1: win0, win1
            #pragma unroll
            for (int j = 0; j < 6; j++) {   // 192 vec4 full-warp
                int v = lane + j * 32;
                float4 rv = __ldg(&row4[v]);
                float4 m0 = sm0[v];
                float4 m1 = sm1[v];
                float c0 = rv.x * m0.x;
                c0 = fmaf(rv.y, m0.y, c0);
                c0 = fmaf(rv.z, m0.z, c0);
                c0 = fmaf(rv.w, m0.w, c0);
                float c1 = rv.x * m1.x;
                c1 = fmaf(rv.y, m1.y, c1);
                c1 = fmaf(rv.z, m1.z, c1);
                c1 = fmaf(rv.w, m1.w, c1);
                if (v < WIN / 4) { s00 += c0; s10 += c1; }
                else             { s01 += c0; s11 += c1; }
            }
            if (lane < NV4S - 192) {        // tail: vec4 192..199 (all win1)
                int v = 192 + lane;
                float4 rv = __ldg(&row4[v]);
                float4 m0 = sm0[v];
                float4 m1 = sm1[v];
                float c0 = rv.x * m0.x;
                c0 = fmaf(rv.y, m0.y, c0);
                c0 = fmaf(rv.z, m0.z, c0);
                c0 = fmaf(rv.w, m0.w, c0);
                float c1 = rv.x * m1.x;
                c1 = fmaf(rv.y, m1.y, c1);
                c1 = fmaf(rv.z, m1.z, c1);
                c1 = fmaf(rv.w, m1.w, c1);
                s01 += c0; s11 += c1;
            }
            // Warp reductions (4 values)
            #pragma unroll
            for (int off = 16; off > 0; off >>= 1) {
                s00 += __shfl_down_sync(0xffffffffu, s00, off);
                s01 += __shfl_down_sync(0xffffffffu, s01, off);
                s10 += __shfl_down_sync(0xffffffffu, s10, off);
                s11 += __shfl_down_sync(0xffffffffu, s11, off);
            }
            if (lane == 0) {
                sm_scores[0][0][r] = s00 * (1.0f / WIN);
                sm_scores[0][1][r] = s01 * (1.0f / WIN);
                sm_scores[1][0][r] = s10 * (1.0f / WIN);
                sm_scores[1][1][r] = s11 * (1.0f / WIN);
            }
        }
    }
    __syncthreads();

    // Top-K (K=8) over 64 refs; warps 0..3 handle (b, win) combos.
    if (warp < BNUM * WPC) {
        const int b   = warp >> 1;
        const int win = warp & 1;
        float v0 = sm_scores[b][win][lane];
        float v1 = sm_scores[b][win][lane + 32];
        float acc = 0.f;

        const int  wglob = wg * WPC + win;
        const long ow    = ((long)b * ANUM + a) * W + wglob;
        const long ibase = (long)BNUM * ANUM * W + ow * KSEL;

        #pragma unroll
        for (int k = 0; k < KSEL; k++) {
            float bv; int bi;
            if (v0 >= v1) { bv = v0; bi = lane; }        // ties -> lower index
            else          { bv = v1; bi = lane + 32; }
            #pragma unroll
            for (int off = 16; off > 0; off >>= 1) {
                float ov = __shfl_xor_sync(0xffffffffu, bv, off);
                int   oi = __shfl_xor_sync(0xffffffffu, bi, off);
                if (ov > bv || (ov == bv && oi < bi)) { bv = ov; bi = oi; }
            }
            acc = fmaf(bv, sm_w[k], acc);
            if (write_idx && lane == 0) out[ibase + k] = (float)bi;
            if (bi == lane)      v0 = -CUDART_INF_F;
            if (bi == lane + 32) v1 = -CUDART_INF_F;
        }
        if (lane == 0) out[ow] = acc;
    }
}

extern "C" void kernel_launch(void* const* d_in, const int* in_sizes, int n_in,
                              void* d_out, int out_size) {
    const float* mixed   = (const float*)d_in[0];
    const float* ref     = (const float*)d_in[1];
    const float* weights = (const float*)d_in[2];
    float* out = (float*)d_out;

    const int S = in_sizes[0] / BNUM;      // 400000
    const int W = S / WIN;                 // 1000
    const int write_idx = (out_size >= BNUM * ANUM * W * (1 + KSEL)) ? 1 : 0;

    dim3 grid(W / WPC, ANUM);              // (500, 3) = 1500 CTAs
    win_topk_kernel<<<grid, 256>>>(mixed, ref, weights, out, S, W, write_idx);
}

// round 11
// speedup vs baseline: 1.2924x; 1.1057x over previous
#include <cuda_runtime.h>
#include <math_constants.h>

#define WIN   400
#define RNUM  64
#define BNUM  2
#define ANUM  3
#define KSEL  8
#define WPC   2                 // windows per CTA
#define SPAN  (WIN * WPC)       // 800 floats
#define NV4S  (SPAN / 4)        // 200 float4 per row span

__global__ __launch_bounds__(256) void win_topk_kernel(
    const float* __restrict__ mixed,    // [B, S]
    const float* __restrict__ ref,      // [A, R, S]
    const float* __restrict__ weights,  // [K]
    float* __restrict__ out,            // [6*W] scores ++ [6*W*K] idx (as float)
    int S, int W, int write_idx)
{
    const int wg   = blockIdx.x;        // window-pair index
    const int a    = blockIdx.y;
    const int tid  = threadIdx.x;
    const int warp = tid >> 5;
    const int lane = tid & 31;

    __shared__ __align__(16) float sm_mixed[BNUM][SPAN];
    __shared__ float sm_scores[BNUM][WPC][RNUM];
    __shared__ float sm_w[KSEL];

    const long base = (long)wg * SPAN;

    // Stage mixed span (both batch rows) into shared, vectorized.
    {
        const float4* m4 = (const float4*)mixed;  // S % 4 == 0, base % 4 == 0
        float4* sm4 = (float4*)&sm_mixed[0][0];
        const int nv = BNUM * NV4S;  // 400 float4
        for (int i = tid; i < nv; i += blockDim.x) {
            int b = i / NV4S, v = i % NV4S;
            sm4[b * NV4S + v] = m4[((long)b * S + base) / 4 + v];
        }
        if (tid < KSEL) sm_w[tid] = weights[tid];
    }
    __syncthreads();

    // Each warp streams 8 ref rows over the 3200B span (2 windows, 2 batches).
    {
        const float4* sm0 = (const float4*)&sm_mixed[0][0];
        const float4* sm1 = (const float4*)&sm_mixed[1][0];
        const float* refa = ref + ((long)a * RNUM) * S + base;

        #pragma unroll
        for (int i = 0; i < RNUM / 8; i++) {
            const int r = warp * (RNUM / 8) + i;
            const float4* row4 = (const float4*)(refa + (long)r * S);

            float s00 = 0.f, s01 = 0.f;   // batch0: win0, win1
            float s10 = 0.f, s11 = 0.f;   // batch1: win0, win1
            #pragma unroll
            for (int j = 0; j < 6; j++) {   // 192 vec4 full-warp
                int v = lane + j * 32;
                float4 rv = __ldcs(&row4[v]);
                float4 m0 = sm0[v];
                float4 m1 = sm1[v];
                float c0 = rv.x * m0.x;
                c0 = fmaf(rv.y, m0.y, c0);
                c0 = fmaf(rv.z, m0.z, c0);
                c0 = fmaf(rv.w, m0.w, c0);
                float c1 = rv.x * m1.x;
                c1 = fmaf(rv.y, m1.y, c1);
                c1 = fmaf(rv.z, m1.z, c1);
                c1 = fmaf(rv.w, m1.w, c1);
                if (v < WIN / 4) { s00 += c0; s10 += c1; }
                else             { s01 += c0; s11 += c1; }
            }
            if (lane < NV4S - 192) {        // tail: vec4 192..199 (all win1)
                int v = 192 + lane;
                float4 rv = __ldcs(&row4[v]);
                float4 m0 = sm0[v];
                float4 m1 = sm1[v];
                float c0 = rv.x * m0.x;
                c0 = fmaf(rv.y, m0.y, c0);
                c0 = fmaf(rv.z, m0.z, c0);
                c0 = fmaf(rv.w, m0.w, c0);
                float c1 = rv.x * m1.x;
                c1 = fmaf(rv.y, m1.y, c1);
                c1 = fmaf(rv.z, m1.z, c1);
                c1 = fmaf(rv.w, m1.w, c1);
                s01 += c0; s11 += c1;
            }
            // Warp reductions (4 values)
            #pragma unroll
            for (int off = 16; off > 0; off >>= 1) {
                s00 += __shfl_down_sync(0xffffffffu, s00, off);
                s01 += __shfl_down_sync(0xffffffffu, s01, off);
                s10 += __shfl_down_sync(0xffffffffu, s10, off);
                s11 += __shfl_down_sync(0xffffffffu, s11, off);
            }
            if (lane == 0) {
                sm_scores[0][0][r] = s00 * (1.0f / WIN);
                sm_scores[0][1][r] = s01 * (1.0f / WIN);
                sm_scores[1][0][r] = s10 * (1.0f / WIN);
                sm_scores[1][1][r] = s11 * (1.0f / WIN);
            }
        }
    }
    __syncthreads();

    // Top-K (K=8) over 64 refs; warps 0..3 handle (b, win) combos.
    if (warp < BNUM * WPC) {
        const int b   = warp >> 1;
        const int win = warp & 1;
        float v0 = sm_scores[b][win][lane];
        float v1 = sm_scores[b][win][lane + 32];
        float acc = 0.f;

        const int  wglob = wg * WPC + win;
        const long ow    = ((long)b * ANUM + a) * W + wglob;
        const long ibase = (long)BNUM * ANUM * W + ow * KSEL;

        #pragma unroll
        for (int k = 0; k < KSEL; k++) {
            float bv; int bi;
            if (v0 >= v1) { bv = v0; bi = lane; }        // ties -> lower index
            else          { bv = v1; bi = lane + 32; }
            #pragma unroll
            for (int off = 16; off > 0; off >>= 1) {
                float ov = __shfl_xor_sync(0xffffffffu, bv, off);
                int   oi = __shfl_xor_sync(0xffffffffu, bi, off);
                if (ov > bv || (ov == bv && oi < bi)) { bv = ov; bi = oi; }
            }
            acc = fmaf(bv, sm_w[k], acc);
            if (write_idx && lane == 0) out[ibase + k] = (float)bi;
            if (bi == lane)      v0 = -CUDART_INF_F;
            if (bi == lane + 32) v1 = -CUDART_INF_F;
        }
        if (lane == 0) out[ow] = acc;
    }
}

extern "C" void kernel_launch(void* const* d_in, const int* in_sizes, int n_in,
                              void* d_out, int out_size) {
    const float* mixed   = (const float*)d_in[0];
    const float* ref     = (const float*)d_in[1];
    const float* weights = (const float*)d_in[2];
    float* out = (float*)d_out;

    const int S = in_sizes[0] / BNUM;      // 400000
    const int W = S / WIN;                 // 1000
    const int write_idx = (out_size >= BNUM * ANUM * W * (1 + KSEL)) ? 1 : 0;

    dim3 grid(W / WPC, ANUM);              // (500, 3) = 1500 CTAs
    win_topk_kernel<<<grid, 256>>>(mixed, ref, weights, out, S, W, write_idx);
}